// round 5
// baseline (speedup 1.0000x reference)
#include <cuda_runtime.h>
#include <cuda_bf16.h>

#define NG 1024
#define DG 128
#define HG 256
#define JCH 8            // j-split factor
#define JW (NG / JCH)    // 128 j per chunk

typedef unsigned long long u64;

// ---- scratch (no allocations allowed) ----
__device__ float g_src[NG * HG];            // X @ W1a^T + b1
__device__ float g_nbr[NG * HG];            // X @ W1b^T
__device__ float g_part[JCH][NG * HG];      // per-j-chunk partials (8MB)
__device__ float g_degp[JCH][NG];           // per-chunk degree partials
__device__ float g_msg[NG * DG];
__device__ float g_gi[NG * 3 * DG];
__device__ float g_gh[NG * 3 * DG];

// ---- packed f32x2 helpers (Blackwell) ----
__device__ __forceinline__ u64 pk2(float lo, float hi) {
    u64 r; asm("mov.b64 %0, {%1, %2};" : "=l"(r) : "f"(lo), "f"(hi)); return r;
}
__device__ __forceinline__ float2 upk(u64 v) {
    float2 r; asm("mov.b64 {%0, %1}, %2;" : "=f"(r.x), "=f"(r.y) : "l"(v)); return r;
}
__device__ __forceinline__ u64 add2(u64 a, u64 b) {
    u64 r; asm("add.rn.f32x2 %0, %1, %2;" : "=l"(r) : "l"(a), "l"(b)); return r;
}
__device__ __forceinline__ void fma2(u64& acc, u64 a, u64 b) {
    asm("fma.rn.f32x2 %0, %1, %2, %0;" : "+l"(acc) : "l"(a), "l"(b));
}

// ============================================================
// BM=32 x BN=64 x BK=32 GEMM tile body. 256 threads, 2x4 microtile (f32x2).
// C = A@B^T (+ rowscale*bias). If FOLD: A element = sum of JCH partial slabs
// (stride NG*HG floats); rowscale from g_degp row-sums.
// ============================================================
template<bool FOLD>
__device__ __forceinline__ void gemm32_tile(
    float (*As)[32], float (*Bs)[64],
    const float* __restrict__ A, int lda,
    const float* __restrict__ B, int ldb,
    const float* __restrict__ bias,
    const float* __restrict__ degp,   // [JCH][NG] flattened, or null
    float* __restrict__ C, int ldc,
    int K, int row0, int col0)
{
    const int tid = threadIdx.x;
    const int tc = tid & 15;        // 0..15 -> 4 cols each
    const int tr = tid >> 4;        // 0..15 -> 2 rows each

    u64 acc2[2][2];
    acc2[0][0] = acc2[0][1] = acc2[1][0] = acc2[1][1] = 0ull;

    for (int k0 = 0; k0 < K; k0 += 32) {
        // A tile: 32 rows x 32 k, one float4 per thread
        {
            int r  = tid >> 3;                 // 0..31
            int c4 = (tid & 7) * 4;            // 0..28
            size_t off = (size_t)(row0 + r) * lda + k0 + c4;
            float4 va;
            if (FOLD) {
                va = *(const float4*)(A + off);
#pragma unroll
                for (int c = 1; c < JCH; ++c) {
                    float4 v = *(const float4*)(A + (size_t)c * (NG * HG) + off);
                    va.x += v.x; va.y += v.y; va.z += v.z; va.w += v.w;
                }
            } else {
                va = *(const float4*)(A + off);
            }
            As[c4 + 0][r] = va.x; As[c4 + 1][r] = va.y;
            As[c4 + 2][r] = va.z; As[c4 + 3][r] = va.w;
        }
        // B tile: 64 rows x 32 k, two float4 per thread
#pragma unroll
        for (int it = 0; it < 2; ++it) {
            int idx = tid + it * 256;          // 0..511
            int r   = idx >> 3;                // 0..63
            int c4  = (idx & 7) * 4;
            float4 vb = *(const float4*)(B + (size_t)(col0 + r) * ldb + k0 + c4);
            Bs[c4 + 0][r] = vb.x; Bs[c4 + 1][r] = vb.y;
            Bs[c4 + 2][r] = vb.z; Bs[c4 + 3][r] = vb.w;
        }
        __syncthreads();
#pragma unroll
        for (int k = 0; k < 32; ++k) {
            float2 a = *(const float2*)&As[k][tr * 2];
            float4 b = *(const float4*)&Bs[k][tc * 4];
            u64 b01 = pk2(b.x, b.y);
            u64 b23 = pk2(b.z, b.w);
            u64 ar;
            ar = pk2(a.x, a.x); fma2(acc2[0][0], ar, b01); fma2(acc2[0][1], ar, b23);
            ar = pk2(a.y, a.y); fma2(acc2[1][0], ar, b01); fma2(acc2[1][1], ar, b23);
        }
        __syncthreads();
    }

#pragma unroll
    for (int r = 0; r < 2; ++r) {
        int row = row0 + tr * 2 + r;
        float rs = 1.f;
        if (degp) {
            float d = 0.f;
#pragma unroll
            for (int c = 0; c < JCH; ++c) d += degp[c * NG + row];
            rs = d;
        }
#pragma unroll
        for (int cp = 0; cp < 2; ++cp) {
            float2 f = upk(acc2[r][cp]);
            int col = col0 + tc * 4 + cp * 2;
            float v0 = f.x, v1 = f.y;
            if (bias) { v0 = fmaf(rs, bias[col], v0); v1 = fmaf(rs, bias[col + 1], v1); }
            C[(size_t)row * ldc + col]     = v0;
            C[(size_t)row * ldc + col + 1] = v1;
        }
    }
}

// ============================================================
// Generic BM=32 GEMM (gi)
// ============================================================
__global__ __launch_bounds__(256) void gemm32_bias_kernel(
    const float* __restrict__ A, int lda,
    const float* __restrict__ B, int ldb,
    const float* __restrict__ bias,
    float* __restrict__ C, int ldc,
    int K)
{
    __shared__ float As[32][32];
    __shared__ float Bs[32][64];
    gemm32_tile<false>(As, Bs, A, lda, B, ldb, bias, nullptr, C, ldc, K,
                       blockIdx.y * 32, blockIdx.x * 64);
}

// ============================================================
// msg GEMM with folded partial-reduction + deg rowscale:
// msg = (sum_c part[c]) @ W2^T + deg * b2
// ============================================================
__global__ __launch_bounds__(256) void gemm32_msg_kernel(
    const float* __restrict__ partBase,   // g_part[0]
    const float* __restrict__ W2,
    const float* __restrict__ b2,
    const float* __restrict__ degp,       // g_degp flattened
    float* __restrict__ msg)
{
    __shared__ float As[32][32];
    __shared__ float Bs[32][64];
    gemm32_tile<true>(As, Bs, partBase, HG, W2, HG, b2, degp, msg, DG, HG,
                      blockIdx.y * 32, blockIdx.x * 64);
}

// ============================================================
// Fused X-GEMM: src | nbr | gh  (all consume X, K=128), BM=32
// grid.x: 0-3 -> src (W1a + b1), 4-7 -> nbr (W1b), 8-13 -> gh (W_hh + b_hh)
// ============================================================
__global__ __launch_bounds__(256) void gemm32_fusedX_kernel(
    const float* __restrict__ X,
    const float* __restrict__ W1,
    const float* __restrict__ b1,
    const float* __restrict__ W_hh,
    const float* __restrict__ b_hh,
    float* __restrict__ src,
    float* __restrict__ nbr,
    float* __restrict__ gh)
{
    __shared__ float As[32][32];
    __shared__ float Bs[32][64];
    const int bx = blockIdx.x;
    const int row0 = blockIdx.y * 32;

    const float* B; int ldb; const float* bias; float* C; int ldc; int col0;
    if (bx < 4)       { B = W1;        ldb = 2 * DG; bias = b1;   C = src; ldc = HG;  col0 = bx * 64; }
    else if (bx < 8)  { B = W1 + DG;   ldb = 2 * DG; bias = 0;    C = nbr; ldc = HG;  col0 = (bx - 4) * 64; }
    else              { B = W_hh;      ldb = DG;     bias = b_hh; C = gh;  ldc = 384; col0 = (bx - 8) * 64; }

    gemm32_tile<false>(As, Bs, X, DG, B, ldb, bias, nullptr, C, ldc, DG, row0, col0);
}

// ============================================================
// part[jb][i,h] = sum_{j in chunk jb} mask[i,j] * relu(src[i,h] + nbr[j,h])
// Grid: (NG/8, JCH). CTA: 8 i-rows x 256 h, j-chunk of 128. f32x2 packed.
// ============================================================
__global__ __launch_bounds__(256, 5) void agg_part_kernel(const int* __restrict__ adj)
{
    __shared__ __align__(16) float msh[JW][8];
    const int i0 = blockIdx.x * 8;
    const int jb = blockIdx.y;
    const int j0 = jb * JW;
    const int tid = threadIdx.x;

#pragma unroll
    for (int it = 0; it < 4; ++it) {
        int idx = tid + it * 256;          // 0..1023
        int t = idx >> 7;                  // 0..7
        int j = idx & 127;
        msh[j][t] = (adj[(size_t)(i0 + t) * NG + j0 + j] > 0) ? 1.f : 0.f;
    }
    __syncthreads();

    // degree partials: warp w handles row t=w
    {
        int w = tid >> 5, lane = tid & 31;
        float ds = 0.f;
#pragma unroll
        for (int k = 0; k < 4; ++k) ds += msh[lane + 32 * k][w];
#pragma unroll
        for (int off = 16; off > 0; off >>= 1)
            ds += __shfl_down_sync(0xFFFFFFFFu, ds, off);
        if (lane == 0) g_degp[jb][i0 + w] = ds;
    }

    const int h = tid;
    u64 s2[4], acc2[4];
#pragma unroll
    for (int p = 0; p < 4; ++p) {
        s2[p] = pk2(g_src[(size_t)(i0 + 2 * p) * HG + h],
                    g_src[(size_t)(i0 + 2 * p + 1) * HG + h]);
        acc2[p] = 0ull;
    }
    const float* nb = g_nbr + (size_t)j0 * HG + h;

#pragma unroll 4
    for (int j = 0; j < JW; ++j) {
        float nv = __ldg(nb + (size_t)j * HG);
        u64 nv2 = pk2(nv, nv);
        ulonglong2 ma = *(const ulonglong2*)&msh[j][0];
        ulonglong2 mb = *(const ulonglong2*)&msh[j][4];
        {
            u64 t = add2(s2[0], nv2); float2 f = upk(t);
            f.x = fmaxf(f.x, 0.f); f.y = fmaxf(f.y, 0.f);
            fma2(acc2[0], ma.x, pk2(f.x, f.y));
        }
        {
            u64 t = add2(s2[1], nv2); float2 f = upk(t);
            f.x = fmaxf(f.x, 0.f); f.y = fmaxf(f.y, 0.f);
            fma2(acc2[1], ma.y, pk2(f.x, f.y));
        }
        {
            u64 t = add2(s2[2], nv2); float2 f = upk(t);
            f.x = fmaxf(f.x, 0.f); f.y = fmaxf(f.y, 0.f);
            fma2(acc2[2], mb.x, pk2(f.x, f.y));
        }
        {
            u64 t = add2(s2[3], nv2); float2 f = upk(t);
            f.x = fmaxf(f.x, 0.f); f.y = fmaxf(f.y, 0.f);
            fma2(acc2[3], mb.y, pk2(f.x, f.y));
        }
    }

    float* p = g_part[jb];
#pragma unroll
    for (int t = 0; t < 4; ++t) {
        float2 f = upk(acc2[t]);
        p[(size_t)(i0 + 2 * t) * HG + h]     = f.x;
        p[(size_t)(i0 + 2 * t + 1) * HG + h] = f.y;
    }
}

// ============================================================
// GRU elementwise:  out = (1-z)*n + z*h
// ============================================================
__global__ __launch_bounds__(256) void gru_kernel(const float* __restrict__ X,
                                                  float* __restrict__ out)
{
    int idx = blockIdx.x * 256 + threadIdx.x;   // 0..131071
    int i = idx >> 7;
    int d = idx & 127;
    const float* gi = g_gi + (size_t)i * 384;
    const float* gh = g_gh + (size_t)i * 384;
    float r = 1.f / (1.f + __expf(-(gi[d] + gh[d])));
    float z = 1.f / (1.f + __expf(-(gi[128 + d] + gh[128 + d])));
    float n = tanhf(gi[256 + d] + r * gh[256 + d]);
    float hprev = X[idx];
    out[idx] = (1.f - z) * n + z * hprev;
}

// ============================================================
extern "C" void kernel_launch(void* const* d_in, const int* in_sizes, int n_in,
                              void* d_out, int out_size)
{
    (void)in_sizes; (void)n_in; (void)out_size;
    const float* X    = (const float*)d_in[0];   // [1024,128]
    const int*   adj  = (const int*)  d_in[1];   // [1024,1024]
    const float* W1   = (const float*)d_in[2];   // [256,256]
    const float* b1   = (const float*)d_in[3];   // [256]
    const float* W2   = (const float*)d_in[4];   // [128,256]
    const float* b2   = (const float*)d_in[5];   // [128]
    const float* W_ih = (const float*)d_in[6];   // [384,128]
    const float* W_hh = (const float*)d_in[7];   // [384,128]
    const float* b_ih = (const float*)d_in[8];   // [384]
    const float* b_hh = (const float*)d_in[9];   // [384]
    float* out = (float*)d_out;

    float *src, *nbr, *part, *degp, *msg, *gi, *gh;
    cudaGetSymbolAddress((void**)&src,  g_src);
    cudaGetSymbolAddress((void**)&nbr,  g_nbr);
    cudaGetSymbolAddress((void**)&part, g_part);
    cudaGetSymbolAddress((void**)&degp, g_degp);
    cudaGetSymbolAddress((void**)&msg,  g_msg);
    cudaGetSymbolAddress((void**)&gi,   g_gi);
    cudaGetSymbolAddress((void**)&gh,   g_gh);

    // src | nbr | gh in one launch (448 CTAs)
    gemm32_fusedX_kernel<<<dim3(14, NG / 32), 256>>>(X, W1, b1, W_hh, b_hh, src, nbr, gh);
    // masked relu aggregation, j-split into JCH partial slabs (+deg partials)
    agg_part_kernel<<<dim3(NG / 8, JCH), 256>>>(adj);
    // msg = (sum partials) @ W2^T + deg*b2   (reduction folded into A-load)
    gemm32_msg_kernel<<<dim3(DG / 64, NG / 32), 256>>>(part, W2, b2, degp, msg);
    // gi = msg @ W_ih^T + b_ih  (192 CTAs)
    gemm32_bias_kernel<<<dim3(384 / 64, NG / 32), 256>>>(msg, DG, W_ih, DG, b_ih, gi, 384, DG);
    // GRU gates + output
    gru_kernel<<<(NG * DG) / 256, 256>>>(X, out);
}